// round 1
// baseline (speedup 1.0000x reference)
#include <cuda_runtime.h>
#include <cuda_bf16.h>
#include <float.h>
#include <math.h>

// Problem constants (fixed by the dataset)
constexpr int Bc = 1024;
constexpr int Sc = 200;
constexpr int Dc = 128;
constexpr int Hc = 128;
constexpr int Nc = 64;
constexpr int ROWS = Bc * Sc;            // 204800
constexpr int OUT_CONCAT = Bc * (Dc + 1); // 132096

// Scratch (device globals; no allocation allowed)
__device__ float g_P[Sc * Hc];          // pos_series @ Wp
__device__ float g_scores[ROWS];        // attention scores
__device__ float g_posloss[Bc];
__device__ float g_negsum[Bc];
__device__ int   g_mask_mode;           // 0=int32, 1=float32, 2=uint8

__device__ __forceinline__ float softplus_f(float x) {
    return fmaxf(x, 0.f) + log1pf(expf(-fabsf(x)));
}

__device__ __forceinline__ int mask_at(const void* m, int idx, int mode) {
    if (mode == 2) return ((const unsigned char*)m)[idx] != 0;
    if (mode == 1) return ((const float*)m)[idx] != 0.f;
    return ((const int*)m)[idx] != 0;
}

// ---------------- mask dtype detection ----------------
__global__ void k_detect(const unsigned int* m) {
    __shared__ int s_bad, s_f32;
    if (threadIdx.x == 0) { s_bad = 0; s_f32 = 0; }
    __syncthreads();
    int bad = 0, f = 0;
    // Scan first B*S bytes (valid for every candidate dtype).
    for (int i = threadIdx.x; i < (Bc * Sc) / 4; i += blockDim.x) {
        unsigned v = m[i];
        if (v == 0x3F800000u) f = 1;
        else if (v > 1u) bad = 1;
    }
    if (bad) atomicOr(&s_bad, 1);
    if (f)   atomicOr(&s_f32, 1);
    __syncthreads();
    if (threadIdx.x == 0) g_mask_mode = s_bad ? 2 : (s_f32 ? 1 : 0);
}

// ---------------- P = pos_series @ Wp  [S,H] ----------------
__global__ void k0_P(const float* __restrict__ pos, const float* __restrict__ Wp) {
    int s = blockIdx.x, h = threadIdx.x;
    float acc = 0.f;
#pragma unroll 8
    for (int d = 0; d < Dc; d++)
        acc = fmaf(__ldg(&pos[s * Dc + d]), __ldg(&Wp[d * Hc + h]), acc);
    g_P[s * Hc + h] = acc;
}

// ---------------- scores: z . tanh(X @ We + P) ----------------
// Block: 256 threads (8 warps). smem: We (64KB) + 16 x-rows (8KB) + z.
// Each warp: 2 rows; each lane: 4 h-columns (float4 of We).
__global__ void k1_scores(const float* __restrict__ X,
                          const float* __restrict__ z,
                          const float* __restrict__ We) {
    extern __shared__ float sm[];
    float* We_s = sm;                 // 16384 floats
    float* x_s  = sm + Dc * Hc;       // 16*128 = 2048 floats
    float* z_s  = x_s + 16 * Dc;      // 128 floats
    const int tid = threadIdx.x;

    float4* We_s4 = (float4*)We_s;
    const float4* We_g4 = (const float4*)We;
    for (int i = tid; i < (Dc * Hc) / 4; i += 256) We_s4[i] = We_g4[i];
    if (tid < Hc) z_s[tid] = z[tid];
    __syncthreads();

    const int w = tid >> 5, l = tid & 31;

    for (int c = 0; c < 4; c++) {
        const int row_base = blockIdx.x * 64 + c * 16;
        // load 16 rows of X (512 float4)
        const float4* Xg4 = (const float4*)(X + (size_t)row_base * Dc);
        float4* xs4 = (float4*)x_s;
        for (int i = tid; i < 512; i += 256) xs4[i] = Xg4[i];
        __syncthreads();

        const int r0 = 2 * w, r1 = 2 * w + 1;
        const int gr0 = row_base + r0, gr1 = row_base + r1;
        const int s0 = gr0 % Sc, s1 = gr1 % Sc;
        float4 a0 = *(const float4*)&g_P[s0 * Hc + 4 * l];
        float4 a1 = *(const float4*)&g_P[s1 * Hc + 4 * l];
        const float* x0 = &x_s[r0 * Dc];
        const float* x1 = &x_s[r1 * Dc];

#pragma unroll 8
        for (int d = 0; d < Dc; d++) {
            const float4 wv = We_s4[d * 32 + l];
            const float xa = x0[d];
            const float xb = x1[d];
            a0.x = fmaf(wv.x, xa, a0.x); a0.y = fmaf(wv.y, xa, a0.y);
            a0.z = fmaf(wv.z, xa, a0.z); a0.w = fmaf(wv.w, xa, a0.w);
            a1.x = fmaf(wv.x, xb, a1.x); a1.y = fmaf(wv.y, xb, a1.y);
            a1.z = fmaf(wv.z, xb, a1.z); a1.w = fmaf(wv.w, xb, a1.w);
        }

        const float z0 = z_s[4 * l], z1 = z_s[4 * l + 1], z2 = z_s[4 * l + 2], z3 = z_s[4 * l + 3];
        float v0 = z0 * tanhf(a0.x) + z1 * tanhf(a0.y) + z2 * tanhf(a0.z) + z3 * tanhf(a0.w);
        float v1 = z0 * tanhf(a1.x) + z1 * tanhf(a1.y) + z2 * tanhf(a1.z) + z3 * tanhf(a1.w);
#pragma unroll
        for (int o = 16; o; o >>= 1) {
            v0 += __shfl_xor_sync(0xffffffffu, v0, o);
            v1 += __shfl_xor_sync(0xffffffffu, v1, o);
        }
        if (l == 0) { g_scores[gr0] = v0; g_scores[gr1] = v1; }
        __syncthreads();
    }
}

// ---------------- per-batch: softmax, weighted sum, cos losses ----------------
__global__ void k2_finalize(const float* __restrict__ X,
                            const void* __restrict__ mask,
                            const float* __restrict__ Xitem,
                            const float* __restrict__ origin,
                            float* __restrict__ out) {
    __shared__ float sh_attn[Sc];
    __shared__ __align__(16) float sh_outv[Dc];
    __shared__ float sh_w[4];
    __shared__ float sh_red[16];
    __shared__ float sh_res[4];   // nL, nO, dLO, inner
    __shared__ int   sh_len;

    const int b = blockIdx.x, tid = threadIdx.x;
    const int w = tid >> 5, l = tid & 31;
    const int mode = g_mask_mode;

    // ---- length ----
    int cnt = mask_at(mask, b * Sc + tid, mode);
    if (tid + 128 < Sc) cnt += mask_at(mask, b * Sc + tid + 128, mode);
#pragma unroll
    for (int o = 16; o; o >>= 1) cnt += __shfl_xor_sync(0xffffffffu, cnt, o);
    if (l == 0) sh_w[w] = (float)cnt;
    __syncthreads();
    if (tid == 0) sh_len = (int)(sh_w[0] + sh_w[1] + sh_w[2] + sh_w[3]);
    __syncthreads();
    const int len = sh_len;

    // ---- masked softmax ----
    float sc0 = 0.f, sc1 = 0.f, m0 = -FLT_MAX;
    if (tid < len)        { sc0 = g_scores[b * Sc + tid];        m0 = sc0; }
    if (tid + 128 < len)  { sc1 = g_scores[b * Sc + tid + 128];  m0 = fmaxf(m0, sc1); }
#pragma unroll
    for (int o = 16; o; o >>= 1) m0 = fmaxf(m0, __shfl_xor_sync(0xffffffffu, m0, o));
    __syncthreads();
    if (l == 0) sh_w[w] = m0;
    __syncthreads();
    const float mx = fmaxf(fmaxf(sh_w[0], sh_w[1]), fmaxf(sh_w[2], sh_w[3]));

    float e0 = (tid < len) ? expf(sc0 - mx) : 0.f;
    float e1 = (tid + 128 < len) ? expf(sc1 - mx) : 0.f;
    float ss = e0 + e1;
#pragma unroll
    for (int o = 16; o; o >>= 1) ss += __shfl_xor_sync(0xffffffffu, ss, o);
    __syncthreads();
    if (l == 0) sh_w[w] = ss;
    __syncthreads();
    const float inv = 1.f / (sh_w[0] + sh_w[1] + sh_w[2] + sh_w[3]);
    sh_attn[tid] = e0 * inv;
    if (tid + 128 < Sc) sh_attn[tid + 128] = e1 * inv;
    __syncthreads();

    // ---- weighted sum over X ----
    const float* Xb = X + (size_t)b * Sc * Dc;
    float ao = 0.f;
    for (int s = 0; s < len; s++)
        ao = fmaf(sh_attn[s], __ldg(&Xb[s * Dc + tid]), ao);
    const float lastv = sh_attn[len - 1] * __ldg(&Xb[(len - 1) * Dc + tid]);
    const float outv = ao - lastv;
    sh_outv[tid] = outv;

    // ---- four block reductions ----
    const float xi = __ldg(&Xitem[b * Dc + tid]);
    float r0 = lastv * lastv, r1 = outv * outv, r2 = lastv * outv, r3 = ao * xi;
#pragma unroll
    for (int o = 16; o; o >>= 1) {
        r0 += __shfl_xor_sync(0xffffffffu, r0, o);
        r1 += __shfl_xor_sync(0xffffffffu, r1, o);
        r2 += __shfl_xor_sync(0xffffffffu, r2, o);
        r3 += __shfl_xor_sync(0xffffffffu, r3, o);
    }
    if (l == 0) { sh_red[w] = r0; sh_red[4 + w] = r1; sh_red[8 + w] = r2; sh_red[12 + w] = r3; }
    __syncthreads();
    if (tid < 4)
        sh_res[tid] = sh_red[tid * 4] + sh_red[tid * 4 + 1] + sh_red[tid * 4 + 2] + sh_red[tid * 4 + 3];
    __syncthreads();

    const float normOut = sqrtf(fmaxf(sh_res[1], 1e-12f));

    // ---- concated output ----
    out[b * (Dc + 1) + tid] = ao;
    if (tid == 0) {
        out[b * (Dc + 1) + Dc] = sh_res[3];
        const float cosp = sh_res[2] / (sqrtf(fmaxf(sh_res[0], 1e-12f)) * normOut);
        const float pl = (1.f - cosp) * 0.5f;
        g_posloss[b] = softplus_f(-pl);
    }

    // ---- negatives: warp-per-n ----
    const float o0 = sh_outv[4 * l], o1 = sh_outv[4 * l + 1];
    const float o2 = sh_outv[4 * l + 2], o3 = sh_outv[4 * l + 3];
    const float4* Ob = (const float4*)(origin + (size_t)b * Nc * Dc);
    float nloss = 0.f;
    for (int n = w; n < Nc; n += 4) {
        const float4 og = Ob[n * 32 + l];
        float dot = og.x * o0 + og.y * o1 + og.z * o2 + og.w * o3;
        float nn = og.x * og.x + og.y * og.y + og.z * og.z + og.w * og.w;
#pragma unroll
        for (int o = 16; o; o >>= 1) {
            dot += __shfl_xor_sync(0xffffffffu, dot, o);
            nn  += __shfl_xor_sync(0xffffffffu, nn, o);
        }
        const float cosn = dot / (sqrtf(fmaxf(nn, 1e-12f)) * normOut);
        nloss += softplus_f((1.f - cosn) * 0.5f);
    }
    __syncthreads();
    if (l == 0) sh_w[w] = nloss;
    __syncthreads();
    if (tid == 0) g_negsum[b] = sh_w[0] + sh_w[1] + sh_w[2] + sh_w[3];
}

// ---------------- deterministic pos-loss reduction + aux write ----------------
__global__ void k3_aux(float* __restrict__ out) {
    __shared__ float sw[32];
    const int tid = threadIdx.x;
    float v = g_posloss[tid];
#pragma unroll
    for (int o = 16; o; o >>= 1) v += __shfl_xor_sync(0xffffffffu, v, o);
    if ((tid & 31) == 0) sw[tid >> 5] = v;
    __syncthreads();
    if (tid < 32) {
        float v2 = sw[tid];
#pragma unroll
        for (int o = 16; o; o >>= 1) v2 += __shfl_xor_sync(0xffffffffu, v2, o);
        if (tid == 0) sw[0] = v2;
    }
    __syncthreads();
    const float tot = sw[0];
    out[OUT_CONCAT + tid] = tot + g_negsum[tid];
}

extern "C" void kernel_launch(void* const* d_in, const int* in_sizes, int n_in,
                              void* d_out, int out_size) {
    const float* X      = (const float*)d_in[0];
    const float* pos    = (const float*)d_in[1];
    const float* Xitem  = (const float*)d_in[2];
    const void*  mask   = d_in[3];
    const float* origin = (const float*)d_in[4];
    const float* Wp     = (const float*)d_in[5];
    const float* We     = (const float*)d_in[6];
    const float* z      = (const float*)d_in[7];
    float* out = (float*)d_out;

    const int smem1 = (Dc * Hc + 16 * Dc + Hc) * (int)sizeof(float); // 74240 B
    cudaFuncSetAttribute(k1_scores, cudaFuncAttributeMaxDynamicSharedMemorySize, smem1);

    k_detect<<<1, 256>>>((const unsigned int*)mask);
    k0_P<<<Sc, Hc>>>(pos, Wp);
    k1_scores<<<ROWS / 64, 256, smem1>>>(X, z, We);
    k2_finalize<<<Bc, Dc>>>(X, mask, Xitem, origin, out);
    k3_aux<<<1, Bc>>>(out);
}

// round 3
// speedup vs baseline: 2.1692x; 2.1692x over previous
#include <cuda_runtime.h>
#include <cuda_bf16.h>
#include <float.h>
#include <math.h>
#include <cstdint>

// Problem constants
constexpr int Bc = 1024;
constexpr int Sc = 200;
constexpr int Dc = 128;
constexpr int Hc = 128;
constexpr int Nc = 64;
constexpr int ROWS = Bc * Sc;             // 204800
constexpr int TILES = ROWS / 128;         // 1600
constexpr int OUT_CONCAT = Bc * (Dc + 1); // 132096

// Scratch
__device__ float g_P[Sc * Hc];
__device__ float g_scores[ROWS];
__device__ float g_posloss[Bc];
__device__ float g_negsum[Bc];
__device__ int   g_mask_mode;

__device__ __forceinline__ uint32_t smem_u32(const void* p) {
    uint32_t a;
    asm("{ .reg .u64 t; cvta.to.shared.u64 t, %1; cvt.u32.u64 %0, t; }" : "=r"(a) : "l"(p));
    return a;
}

#define LDMX4(r0, r1, r2, r3, addr) \
    asm volatile("ldmatrix.sync.aligned.m8n8.x4.shared.b16 {%0,%1,%2,%3}, [%4];" \
        : "=r"(r0), "=r"(r1), "=r"(r2), "=r"(r3) : "r"(addr))
#define LDMX2(r0, r1, addr) \
    asm volatile("ldmatrix.sync.aligned.m8n8.x2.shared.b16 {%0,%1}, [%2];" \
        : "=r"(r0), "=r"(r1) : "r"(addr))
#define MMA16816(c, a, b) \
    asm volatile("mma.sync.aligned.m16n8k16.row.col.f32.bf16.bf16.f32 " \
        "{%0,%1,%2,%3},{%4,%5,%6,%7},{%8,%9},{%0,%1,%2,%3};" \
        : "+f"((c)[0]), "+f"((c)[1]), "+f"((c)[2]), "+f"((c)[3]) \
        : "r"((a)[0]), "r"((a)[1]), "r"((a)[2]), "r"((a)[3]), "r"((b)[0]), "r"((b)[1]))

// swizzled byte offset inside a 128x128 bf16 tile (256B rows, 16B chunks)
__device__ __forceinline__ uint32_t swz(int row, int chunk) {
    return (uint32_t)(row * 256 + ((chunk ^ (row & 7)) << 4));
}

__device__ __forceinline__ float softplus_f(float x) {
    return fmaxf(x, 0.f) + log1pf(expf(-fabsf(x)));
}
__device__ __forceinline__ float tanh_acc(float x) {
    float t;
    asm("ex2.approx.f32 %0, %1;" : "=f"(t) : "f"(x * 2.8853900817779268f)); // e^{2x}
    float r;
    asm("rcp.approx.f32 %0, %1;" : "=f"(r) : "f"(t + 1.0f));
    return fmaf(-2.0f, r, 1.0f);
}
__device__ __forceinline__ int mask_at(const void* m, int idx, int mode) {
    if (mode == 2) return ((const unsigned char*)m)[idx] != 0;
    if (mode == 1) return ((const float*)m)[idx] != 0.f;
    return ((const int*)m)[idx] != 0;
}

// ===================== mask dtype detection =====================
__global__ void k_detect(const unsigned int* m) {
    __shared__ int s_bad, s_f32;
    if (threadIdx.x == 0) { s_bad = 0; s_f32 = 0; }
    __syncthreads();
    int bad = 0, f = 0;
    for (int i = threadIdx.x; i < (Bc * Sc) / 4; i += blockDim.x) {
        unsigned v = m[i];
        if (v == 0x3F800000u) f = 1;
        else if (v > 1u) bad = 1;
    }
    if (bad) atomicOr(&s_bad, 1);
    if (f)   atomicOr(&s_f32, 1);
    __syncthreads();
    if (threadIdx.x == 0) g_mask_mode = s_bad ? 2 : (s_f32 ? 1 : 0);
}

// ===================== P = pos_series @ Wp =====================
__global__ void k0_P(const float* __restrict__ pos, const float* __restrict__ Wp) {
    int s = blockIdx.x, h = threadIdx.x;
    float acc = 0.f;
#pragma unroll 8
    for (int d = 0; d < Dc; d++)
        acc = fmaf(__ldg(&pos[s * Dc + d]), __ldg(&Wp[d * Hc + h]), acc);
    g_P[s * Hc + h] = acc;
}

// ===================== mma.sync score kernel =====================
// SMEM: A_hi 32KB, A_lo 32KB (reused for WeT staging at init), red 4KB
constexpr int OFF_AHI = 0;
constexpr int OFF_ALO = 32768;
constexpr int OFF_RED = 65536;
constexpr int SMEM_K1 = 65536 + 128 * 8 * 4; // 69632

__global__ void __launch_bounds__(256, 1)
k1_mma(const float* __restrict__ X, const float* __restrict__ We, const float* __restrict__ z) {
    extern __shared__ char smc[];
    const uint32_t smb = smem_u32(smc);
    float* red = (float*)(smc + OFF_RED);
    const int tid = threadIdx.x;
    const int wid = tid >> 5, l = tid & 31;
    const int bn = wid * 16;

    // ---- stage WeT (transposed) hi/lo into A buffers, load B fragments ----
    for (int i = tid; i < Dc * Hc; i += 256) {
        int d = i >> 7, h = i & 127;
        float v = We[i];
        __nv_bfloat16 hi = __float2bfloat16(v);
        __nv_bfloat16 lo = __float2bfloat16(v - __bfloat162float(hi));
        uint32_t a = swz(h, d >> 3) + (uint32_t)((d & 7) * 2);
        *(__nv_bfloat16*)(smc + OFF_AHI + a) = hi;
        *(__nv_bfloat16*)(smc + OFF_ALO + a) = lo;
    }
    __syncthreads();

    uint32_t Bh[8][2][2], Bl[8][2][2];
    {
        const int brow = bn + (l & 7);
        const int bc = (l >> 3) & 1;
#pragma unroll
        for (int ks = 0; ks < 8; ks++) {
#pragma unroll
            for (int j = 0; j < 2; j++) {
                uint32_t a = swz(brow + j * 8, 2 * ks + bc);
                LDMX2(Bh[ks][j][0], Bh[ks][j][1], smb + OFF_AHI + a);
                LDMX2(Bl[ks][j][0], Bl[ks][j][1], smb + OFF_ALO + a);
            }
        }
    }
    // per-thread fixed output columns
    const int c0 = bn + (l & 3) * 2;
    const float zv0 = __ldg(&z[c0]),     zv1 = __ldg(&z[c0 + 1]);
    const float zv2 = __ldg(&z[c0 + 8]), zv3 = __ldg(&z[c0 + 9]);
    __syncthreads();

    // ldmatrix A lane addressing (fixed per thread)
    const int arow_off = (l & 7) + ((l >> 3) & 1) * 8;
    const int achk_off = (l >> 4) & 1;

    for (int t = blockIdx.x; t < TILES; t += gridDim.x) {
        // ---- load + convert X tile ----
        const float4* Xg = (const float4*)(X + (size_t)t * (128 * 128));
#pragma unroll
        for (int jj = 0; jj < 16; jj++) {
            int i4 = tid + jj * 256;
            float4 v = Xg[i4];
            int elem = i4 * 4;
            int row = elem >> 7, col = elem & 127;
            uint32_t a = swz(row, col >> 3) + (uint32_t)((col & 7) * 2);
            __nv_bfloat16 hx = __float2bfloat16(v.x), hy = __float2bfloat16(v.y);
            __nv_bfloat16 hz = __float2bfloat16(v.z), hw = __float2bfloat16(v.w);
            __nv_bfloat16 lx = __float2bfloat16(v.x - __bfloat162float(hx));
            __nv_bfloat16 ly = __float2bfloat16(v.y - __bfloat162float(hy));
            __nv_bfloat16 lz = __float2bfloat16(v.z - __bfloat162float(hz));
            __nv_bfloat16 lw = __float2bfloat16(v.w - __bfloat162float(hw));
            uint2 hh = make_uint2(
                (uint32_t)__bfloat16_as_ushort(hx) | ((uint32_t)__bfloat16_as_ushort(hy) << 16),
                (uint32_t)__bfloat16_as_ushort(hz) | ((uint32_t)__bfloat16_as_ushort(hw) << 16));
            uint2 ll = make_uint2(
                (uint32_t)__bfloat16_as_ushort(lx) | ((uint32_t)__bfloat16_as_ushort(ly) << 16),
                (uint32_t)__bfloat16_as_ushort(lz) | ((uint32_t)__bfloat16_as_ushort(lw) << 16));
            *(uint2*)(smc + OFF_AHI + a) = hh;
            *(uint2*)(smc + OFF_ALO + a) = ll;
        }
        __syncthreads();

        // ---- GEMM: C[128x16 per warp] = Xhi*Whi + Xhi*Wlo + Xlo*Whi ----
        float C[8][2][4];
#pragma unroll
        for (int f = 0; f < 8; f++)
#pragma unroll
            for (int j = 0; j < 2; j++)
#pragma unroll
                for (int q = 0; q < 4; q++) C[f][j][q] = 0.f;

#pragma unroll
        for (int ks = 0; ks < 8; ks++) {
            uint32_t A[8][4];
#pragma unroll
            for (int f = 0; f < 8; f++) {
                uint32_t a = swz(f * 16 + arow_off, 2 * ks + achk_off);
                LDMX4(A[f][0], A[f][1], A[f][2], A[f][3], smb + OFF_AHI + a);
            }
#pragma unroll
            for (int f = 0; f < 8; f++) {
                MMA16816(C[f][0], A[f], Bh[ks][0]);
                MMA16816(C[f][1], A[f], Bh[ks][1]);
                MMA16816(C[f][0], A[f], Bl[ks][0]);
                MMA16816(C[f][1], A[f], Bl[ks][1]);
            }
#pragma unroll
            for (int f = 0; f < 8; f++) {
                uint32_t a = swz(f * 16 + arow_off, 2 * ks + achk_off);
                LDMX4(A[f][0], A[f][1], A[f][2], A[f][3], smb + OFF_ALO + a);
            }
#pragma unroll
            for (int f = 0; f < 8; f++) {
                MMA16816(C[f][0], A[f], Bh[ks][0]);
                MMA16816(C[f][1], A[f], Bh[ks][1]);
            }
        }

        // ---- epilogue: partial z . tanh(C + P) per warp slice ----
        const int mb = t * 128;
#pragma unroll
        for (int f = 0; f < 8; f++) {
            const int r0 = f * 16 + (l >> 2), r1 = r0 + 8;
            const int s0 = (mb + r0) % Sc, s1 = (mb + r1) % Sc;
            float2 p00 = *(const float2*)&g_P[s0 * Hc + c0];
            float2 p01 = *(const float2*)&g_P[s0 * Hc + c0 + 8];
            float2 p10 = *(const float2*)&g_P[s1 * Hc + c0];
            float2 p11 = *(const float2*)&g_P[s1 * Hc + c0 + 8];
            float p0 = zv0 * tanh_acc(C[f][0][0] + p00.x) + zv1 * tanh_acc(C[f][0][1] + p00.y)
                     + zv2 * tanh_acc(C[f][1][0] + p01.x) + zv3 * tanh_acc(C[f][1][1] + p01.y);
            float p1 = zv0 * tanh_acc(C[f][0][2] + p10.x) + zv1 * tanh_acc(C[f][0][3] + p10.y)
                     + zv2 * tanh_acc(C[f][1][2] + p11.x) + zv3 * tanh_acc(C[f][1][3] + p11.y);
            p0 += __shfl_xor_sync(0xffffffffu, p0, 1);
            p0 += __shfl_xor_sync(0xffffffffu, p0, 2);
            p1 += __shfl_xor_sync(0xffffffffu, p1, 1);
            p1 += __shfl_xor_sync(0xffffffffu, p1, 2);
            if ((l & 3) == 0) { red[r0 * 8 + wid] = p0; red[r1 * 8 + wid] = p1; }
        }
        __syncthreads();
        if (tid < 128) {
            float s = 0.f;
#pragma unroll
            for (int w = 0; w < 8; w++) s += red[tid * 8 + w];
            g_scores[mb + tid] = s;
        }
        __syncthreads();
    }
}

// ===================== per-batch finalize =====================
__global__ void k2_finalize(const float* __restrict__ X,
                            const void* __restrict__ mask,
                            const float* __restrict__ Xitem,
                            const float* __restrict__ origin,
                            float* __restrict__ out) {
    __shared__ float sh_attn[Sc];
    __shared__ __align__(16) float sh_outv[Dc];
    __shared__ float sh_w[4];
    __shared__ float sh_red[16];
    __shared__ float sh_res[4];
    __shared__ int   sh_len;

    const int b = blockIdx.x, tid = threadIdx.x;
    const int w = tid >> 5, l = tid & 31;
    const int mode = g_mask_mode;

    int cnt = mask_at(mask, b * Sc + tid, mode);
    if (tid + 128 < Sc) cnt += mask_at(mask, b * Sc + tid + 128, mode);
#pragma unroll
    for (int o = 16; o; o >>= 1) cnt += __shfl_xor_sync(0xffffffffu, cnt, o);
    if (l == 0) sh_w[w] = (float)cnt;
    __syncthreads();
    if (tid == 0) sh_len = (int)(sh_w[0] + sh_w[1] + sh_w[2] + sh_w[3]);
    __syncthreads();
    const int len = sh_len;

    float sc0 = 0.f, sc1 = 0.f, m0 = -FLT_MAX;
    if (tid < len)       { sc0 = g_scores[b * Sc + tid];       m0 = sc0; }
    if (tid + 128 < len) { sc1 = g_scores[b * Sc + tid + 128]; m0 = fmaxf(m0, sc1); }
#pragma unroll
    for (int o = 16; o; o >>= 1) m0 = fmaxf(m0, __shfl_xor_sync(0xffffffffu, m0, o));
    __syncthreads();
    if (l == 0) sh_w[w] = m0;
    __syncthreads();
    const float mx = fmaxf(fmaxf(sh_w[0], sh_w[1]), fmaxf(sh_w[2], sh_w[3]));

    float e0 = (tid < len) ? expf(sc0 - mx) : 0.f;
    float e1 = (tid + 128 < len) ? expf(sc1 - mx) : 0.f;
    float ss = e0 + e1;
#pragma unroll
    for (int o = 16; o; o >>= 1) ss += __shfl_xor_sync(0xffffffffu, ss, o);
    __syncthreads();
    if (l == 0) sh_w[w] = ss;
    __syncthreads();
    const float inv = 1.f / (sh_w[0] + sh_w[1] + sh_w[2] + sh_w[3]);
    sh_attn[tid] = e0 * inv;
    if (tid + 128 < Sc) sh_attn[tid + 128] = e1 * inv;
    __syncthreads();

    const float* Xb = X + (size_t)b * Sc * Dc + tid;
    float a0 = 0.f, a1 = 0.f, a2 = 0.f, a3 = 0.f;
    int s = 0;
    for (; s + 4 <= len; s += 4) {
        a0 = fmaf(sh_attn[s + 0], __ldg(&Xb[(s + 0) * Dc]), a0);
        a1 = fmaf(sh_attn[s + 1], __ldg(&Xb[(s + 1) * Dc]), a1);
        a2 = fmaf(sh_attn[s + 2], __ldg(&Xb[(s + 2) * Dc]), a2);
        a3 = fmaf(sh_attn[s + 3], __ldg(&Xb[(s + 3) * Dc]), a3);
    }
    for (; s < len; s++) a0 = fmaf(sh_attn[s], __ldg(&Xb[s * Dc]), a0);
    const float ao = (a0 + a1) + (a2 + a3);
    const float lastv = sh_attn[len - 1] * __ldg(&Xb[(len - 1) * Dc]);
    const float outv = ao - lastv;
    sh_outv[tid] = outv;

    const float xi = __ldg(&Xitem[b * Dc + tid]);
    float r0 = lastv * lastv, r1 = outv * outv, r2 = lastv * outv, r3 = ao * xi;
#pragma unroll
    for (int o = 16; o; o >>= 1) {
        r0 += __shfl_xor_sync(0xffffffffu, r0, o);
        r1 += __shfl_xor_sync(0xffffffffu, r1, o);
        r2 += __shfl_xor_sync(0xffffffffu, r2, o);
        r3 += __shfl_xor_sync(0xffffffffu, r3, o);
    }
    if (l == 0) { sh_red[w] = r0; sh_red[4 + w] = r1; sh_red[8 + w] = r2; sh_red[12 + w] = r3; }
    __syncthreads();
    if (tid < 4)
        sh_res[tid] = sh_red[tid * 4] + sh_red[tid * 4 + 1] + sh_red[tid * 4 + 2] + sh_red[tid * 4 + 3];
    __syncthreads();

    const float normOut = sqrtf(fmaxf(sh_res[1], 1e-12f));

    out[b * (Dc + 1) + tid] = ao;
    if (tid == 0) {
        out[b * (Dc + 1) + Dc] = sh_res[3];
        const float cosp = sh_res[2] / (sqrtf(fmaxf(sh_res[0], 1e-12f)) * normOut);
        const float pl = (1.f - cosp) * 0.5f;
        g_posloss[b] = softplus_f(-pl);
    }

    const float o0 = sh_outv[4 * l], o1 = sh_outv[4 * l + 1];
    const float o2 = sh_outv[4 * l + 2], o3 = sh_outv[4 * l + 3];
    const float4* Ob = (const float4*)(origin + (size_t)b * Nc * Dc);
    float nloss = 0.f;
    for (int n = w; n < Nc; n += 4) {
        const float4 og = Ob[n * 32 + l];
        float dot = og.x * o0 + og.y * o1 + og.z * o2 + og.w * o3;
        float nn = og.x * og.x + og.y * og.y + og.z * og.z + og.w * og.w;
#pragma unroll
        for (int o = 16; o; o >>= 1) {
            dot += __shfl_xor_sync(0xffffffffu, dot, o);
            nn  += __shfl_xor_sync(0xffffffffu, nn, o);
        }
        const float cosn = dot / (sqrtf(fmaxf(nn, 1e-12f)) * normOut);
        nloss += softplus_f((1.f - cosn) * 0.5f);
    }
    __syncthreads();
    if (l == 0) sh_w[w] = nloss;
    __syncthreads();
    if (tid == 0) g_negsum[b] = sh_w[0] + sh_w[1] + sh_w[2] + sh_w[3];
}

// ===================== aux write =====================
__global__ void k3_aux(float* __restrict__ out) {
    __shared__ float sw[32];
    const int tid = threadIdx.x;
    float v = g_posloss[tid];
#pragma unroll
    for (int o = 16; o; o >>= 1) v += __shfl_xor_sync(0xffffffffu, v, o);
    if ((tid & 31) == 0) sw[tid >> 5] = v;
    __syncthreads();
    if (tid < 32) {
        float v2 = sw[tid];
#pragma unroll
        for (int o = 16; o; o >>= 1) v2 += __shfl_xor_sync(0xffffffffu, v2, o);
        if (tid == 0) sw[0] = v2;
    }
    __syncthreads();
    out[OUT_CONCAT + tid] = sw[0] + g_negsum[tid];
}

extern "C" void kernel_launch(void* const* d_in, const int* in_sizes, int n_in,
                              void* d_out, int out_size) {
    const float* X      = (const float*)d_in[0];
    const float* pos    = (const float*)d_in[1];
    const float* Xitem  = (const float*)d_in[2];
    const void*  mask   = d_in[3];
    const float* origin = (const float*)d_in[4];
    const float* Wp     = (const float*)d_in[5];
    const float* We     = (const float*)d_in[6];
    const float* z      = (const float*)d_in[7];
    float* out = (float*)d_out;

    cudaFuncSetAttribute(k1_mma, cudaFuncAttributeMaxDynamicSharedMemorySize, SMEM_K1);

    k_detect<<<1, 256>>>((const unsigned int*)mask);
    k0_P<<<Sc, Hc>>>(pos, Wp);
    k1_mma<<<148, 256, SMEM_K1>>>(X, We, z);
    k2_finalize<<<Bc, Dc>>>(X, mask, Xitem, origin, out);
    k3_aux<<<1, Bc>>>(out);
}

// round 4
// speedup vs baseline: 2.4716x; 1.1394x over previous
#include <cuda_runtime.h>
#include <cuda_bf16.h>
#include <float.h>
#include <math.h>
#include <cstdint>

// Problem constants
constexpr int Bc = 1024;
constexpr int Sc = 200;
constexpr int Dc = 128;
constexpr int Hc = 128;
constexpr int Nc = 64;
constexpr int ROWS = Bc * Sc;             // 204800
constexpr int TILES = ROWS / 128;         // 1600
constexpr int OUT_CONCAT = Bc * (Dc + 1); // 132096

// Scratch
__device__ float g_P[Sc * Hc];
__device__ float g_scores[ROWS];
__device__ float g_posloss[Bc];
__device__ float g_negsum[Bc];
__device__ int   g_mask_mode;

__device__ __forceinline__ uint32_t smem_u32(const void* p) {
    uint32_t a;
    asm("{ .reg .u64 t; cvta.to.shared.u64 t, %1; cvt.u32.u64 %0, t; }" : "=r"(a) : "l"(p));
    return a;
}

#define LDMX4(r0, r1, r2, r3, addr) \
    asm volatile("ldmatrix.sync.aligned.m8n8.x4.shared.b16 {%0,%1,%2,%3}, [%4];" \
        : "=r"(r0), "=r"(r1), "=r"(r2), "=r"(r3) : "r"(addr))
#define LDMX2(r0, r1, addr) \
    asm volatile("ldmatrix.sync.aligned.m8n8.x2.shared.b16 {%0,%1}, [%2];" \
        : "=r"(r0), "=r"(r1) : "r"(addr))
#define MMA16816(c, a, b) \
    asm volatile("mma.sync.aligned.m16n8k16.row.col.f32.bf16.bf16.f32 " \
        "{%0,%1,%2,%3},{%4,%5,%6,%7},{%8,%9},{%0,%1,%2,%3};" \
        : "+f"((c)[0]), "+f"((c)[1]), "+f"((c)[2]), "+f"((c)[3]) \
        : "r"((a)[0]), "r"((a)[1]), "r"((a)[2]), "r"((a)[3]), "r"((b)[0]), "r"((b)[1]))

// swizzled byte offset inside a 128x128 bf16 tile (256B rows, 16B chunks)
__device__ __forceinline__ uint32_t swz(int row, int chunk) {
    return (uint32_t)(row * 256 + ((chunk ^ (row & 7)) << 4));
}

__device__ __forceinline__ float softplus_f(float x) {
    return fmaxf(x, 0.f) + log1pf(expf(-fabsf(x)));
}
__device__ __forceinline__ float tanh_fast(float x) {
    float t;
    asm("tanh.approx.f32 %0, %1;" : "=f"(t) : "f"(x));
    return t;
}
__device__ __forceinline__ int mask_at(const void* m, int idx, int mode) {
    if (mode == 2) return ((const unsigned char*)m)[idx] != 0;
    if (mode == 1) return ((const float*)m)[idx] != 0.f;
    return ((const int*)m)[idx] != 0;
}

// ===================== mask dtype detection =====================
__global__ void k_detect(const unsigned int* m) {
    __shared__ int s_bad, s_f32;
    if (threadIdx.x == 0) { s_bad = 0; s_f32 = 0; }
    __syncthreads();
    int bad = 0, f = 0;
    for (int i = threadIdx.x; i < (Bc * Sc) / 4; i += blockDim.x) {
        unsigned v = m[i];
        if (v == 0x3F800000u) f = 1;
        else if (v > 1u) bad = 1;
    }
    if (bad) atomicOr(&s_bad, 1);
    if (f)   atomicOr(&s_f32, 1);
    __syncthreads();
    if (threadIdx.x == 0) g_mask_mode = s_bad ? 2 : (s_f32 ? 1 : 0);
}

// ===================== P = pos_series @ Wp =====================
__global__ void k0_P(const float* __restrict__ pos, const float* __restrict__ Wp) {
    int s = blockIdx.x, h = threadIdx.x;
    float acc = 0.f;
#pragma unroll 8
    for (int d = 0; d < Dc; d++)
        acc = fmaf(__ldg(&pos[s * Dc + d]), __ldg(&Wp[d * Hc + h]), acc);
    g_P[s * Hc + h] = acc;
}

// ===================== mma.sync score kernel =====================
constexpr int PSTR = 132;                       // padded P row stride (floats)
constexpr int OFF_AHI = 0;
constexpr int OFF_ALO = 32768;
constexpr int OFF_P   = 65536;                  // Sc*PSTR*4 = 105600
constexpr int OFF_RED = OFF_P + Sc * PSTR * 4;  // 171136; 128*9*4 = 4608
constexpr int SMEM_K1 = OFF_RED + 128 * 9 * 4;  // 175744

// fast fp32 -> bf16 hi/lo split for a float4; hi = top-16-bit truncation
__device__ __forceinline__ void split4(float4 v, uint2& hh, uint2& ll) {
    uint32_t ux = __float_as_uint(v.x), uy = __float_as_uint(v.y);
    uint32_t uz = __float_as_uint(v.z), uw = __float_as_uint(v.w);
    hh.x = __byte_perm(ux, uy, 0x7632);
    hh.y = __byte_perm(uz, uw, 0x7632);
    float lx = v.x - __uint_as_float(ux & 0xFFFF0000u);
    float ly = v.y - __uint_as_float(uy & 0xFFFF0000u);
    float lz = v.z - __uint_as_float(uz & 0xFFFF0000u);
    float lw = v.w - __uint_as_float(uw & 0xFFFF0000u);
    asm("cvt.rn.bf16x2.f32 %0, %1, %2;" : "=r"(ll.x) : "f"(ly), "f"(lx));
    asm("cvt.rn.bf16x2.f32 %0, %1, %2;" : "=r"(ll.y) : "f"(lw), "f"(lz));
}

__global__ void __launch_bounds__(256, 1)
k1_mma(const float* __restrict__ X, const float* __restrict__ We, const float* __restrict__ z) {
    extern __shared__ char smc[];
    const uint32_t smb = smem_u32(smc);
    float* red = (float*)(smc + OFF_RED);
    float* sP  = (float*)(smc + OFF_P);
    const int tid = threadIdx.x;
    const int wid = tid >> 5, l = tid & 31;
    const int bn = wid * 16;

    // ---- stage WeT (transposed) hi/lo into A buffers, load B fragments ----
    for (int i = tid; i < Dc * Hc; i += 256) {
        int d = i >> 7, h = i & 127;
        float v = We[i];
        __nv_bfloat16 hi = __float2bfloat16(v);
        __nv_bfloat16 lo = __float2bfloat16(v - __bfloat162float(hi));
        uint32_t a = swz(h, d >> 3) + (uint32_t)((d & 7) * 2);
        *(__nv_bfloat16*)(smc + OFF_AHI + a) = hi;
        *(__nv_bfloat16*)(smc + OFF_ALO + a) = lo;
    }
    __syncthreads();

    uint32_t Bh[8][2][2], Bl[8][2][2];
    {
        const int brow = bn + (l & 7);
        const int bc = (l >> 3) & 1;
#pragma unroll
        for (int ks = 0; ks < 8; ks++) {
#pragma unroll
            for (int j = 0; j < 2; j++) {
                uint32_t a = swz(brow + j * 8, 2 * ks + bc);
                LDMX2(Bh[ks][j][0], Bh[ks][j][1], smb + OFF_AHI + a);
                LDMX2(Bl[ks][j][0], Bl[ks][j][1], smb + OFF_ALO + a);
            }
        }
    }
    const int c0 = bn + (l & 3) * 2;
    const float zv0 = __ldg(&z[c0]),     zv1 = __ldg(&z[c0 + 1]);
    const float zv2 = __ldg(&z[c0 + 8]), zv3 = __ldg(&z[c0 + 9]);
    __syncthreads();   // B frags read; A buffers now reusable

    // ---- P into padded SMEM ----
    for (int i = tid; i < Sc * 32; i += 256) {
        int r = i >> 5, c4 = (i & 31) * 4;
        float4 v = *(const float4*)&g_P[r * Hc + c4];
        *(float4*)&sP[r * PSTR + c4] = v;
    }

    const int arow_off = (l & 7) + ((l >> 3) & 1) * 8;
    const int achk_off = (l >> 4) & 1;

    const int GD = gridDim.x;
    int t = blockIdx.x;
    float4 pf[16];
    if (t < TILES) {
        const float4* Xg = (const float4*)(X + (size_t)t * (128 * 128));
#pragma unroll
        for (int jj = 0; jj < 16; jj++) pf[jj] = Xg[tid + jj * 256];
    }
    __syncthreads();

    for (; t < TILES; t += GD) {
        // ---- convert + store prefetched tile ----
#pragma unroll
        for (int jj = 0; jj < 16; jj++) {
            int i4 = tid + jj * 256;
            int elem = i4 * 4;
            int row = elem >> 7, col = elem & 127;
            uint32_t a = swz(row, col >> 3) + (uint32_t)((col & 7) * 2);
            uint2 hh, ll;
            split4(pf[jj], hh, ll);
            *(uint2*)(smc + OFF_AHI + a) = hh;
            *(uint2*)(smc + OFF_ALO + a) = ll;
        }
        __syncthreads();

        // ---- GEMM: C[128x16 per warp] = Xhi*Whi + Xhi*Wlo + Xlo*Whi ----
        float C[8][2][4];
#pragma unroll
        for (int f = 0; f < 8; f++)
#pragma unroll
            for (int j = 0; j < 2; j++)
#pragma unroll
                for (int q = 0; q < 4; q++) C[f][j][q] = 0.f;

#pragma unroll
        for (int ks = 0; ks < 8; ks++) {
            uint32_t A[8][4];
#pragma unroll
            for (int f = 0; f < 8; f++) {
                uint32_t a = swz(f * 16 + arow_off, 2 * ks + achk_off);
                LDMX4(A[f][0], A[f][1], A[f][2], A[f][3], smb + OFF_AHI + a);
            }
#pragma unroll
            for (int f = 0; f < 8; f++) {
                MMA16816(C[f][0], A[f], Bh[ks][0]);
                MMA16816(C[f][1], A[f], Bh[ks][1]);
                MMA16816(C[f][0], A[f], Bl[ks][0]);
                MMA16816(C[f][1], A[f], Bl[ks][1]);
            }
#pragma unroll
            for (int f = 0; f < 8; f++) {
                uint32_t a = swz(f * 16 + arow_off, 2 * ks + achk_off);
                LDMX4(A[f][0], A[f][1], A[f][2], A[f][3], smb + OFF_ALO + a);
            }
#pragma unroll
            for (int f = 0; f < 8; f++) {
                MMA16816(C[f][0], A[f], Bh[ks][0]);
                MMA16816(C[f][1], A[f], Bh[ks][1]);
            }
        }

        // ---- prefetch next tile (latency hidden by epilogue) ----
        const int tn = t + GD;
        if (tn < TILES) {
            const float4* Xg = (const float4*)(X + (size_t)tn * (128 * 128));
#pragma unroll
            for (int jj = 0; jj < 16; jj++) pf[jj] = Xg[tid + jj * 256];
        }

        // ---- epilogue: partial z . tanh(C + P) per warp slice ----
        const int mb = t * 128;
#pragma unroll
        for (int f = 0; f < 8; f++) {
            const int r0 = f * 16 + (l >> 2), r1 = r0 + 8;
            const int s0 = (mb + r0) % Sc, s1 = (mb + r1) % Sc;
            float2 p00 = *(const float2*)&sP[s0 * PSTR + c0];
            float2 p01 = *(const float2*)&sP[s0 * PSTR + c0 + 8];
            float2 p10 = *(const float2*)&sP[s1 * PSTR + c0];
            float2 p11 = *(const float2*)&sP[s1 * PSTR + c0 + 8];
            float p0 = zv0 * tanh_fast(C[f][0][0] + p00.x) + zv1 * tanh_fast(C[f][0][1] + p00.y)
                     + zv2 * tanh_fast(C[f][1][0] + p01.x) + zv3 * tanh_fast(C[f][1][1] + p01.y);
            float p1 = zv0 * tanh_fast(C[f][0][2] + p10.x) + zv1 * tanh_fast(C[f][0][3] + p10.y)
                     + zv2 * tanh_fast(C[f][1][2] + p11.x) + zv3 * tanh_fast(C[f][1][3] + p11.y);
            p0 += __shfl_xor_sync(0xffffffffu, p0, 1);
            p0 += __shfl_xor_sync(0xffffffffu, p0, 2);
            p1 += __shfl_xor_sync(0xffffffffu, p1, 1);
            p1 += __shfl_xor_sync(0xffffffffu, p1, 2);
            if ((l & 3) == 0) { red[r0 * 9 + wid] = p0; red[r1 * 9 + wid] = p1; }
        }
        __syncthreads();
        if (tid < 128) {
            float s = 0.f;
#pragma unroll
            for (int w = 0; w < 8; w++) s += red[tid * 9 + w];
            g_scores[mb + tid] = s;
        }
        __syncthreads();
    }
}

// ===================== per-batch finalize =====================
__global__ void k2_finalize(const float* __restrict__ X,
                            const void* __restrict__ mask,
                            const float* __restrict__ Xitem,
                            const float* __restrict__ origin,
                            float* __restrict__ out) {
    __shared__ float sh_attn[Sc];
    __shared__ __align__(16) float sh_outv[Dc];
    __shared__ float sh_w[4];
    __shared__ float sh_red[16];
    __shared__ float sh_res[4];
    __shared__ int   sh_len;

    const int b = blockIdx.x, tid = threadIdx.x;
    const int w = tid >> 5, l = tid & 31;
    const int mode = g_mask_mode;

    int cnt = mask_at(mask, b * Sc + tid, mode);
    if (tid + 128 < Sc) cnt += mask_at(mask, b * Sc + tid + 128, mode);
#pragma unroll
    for (int o = 16; o; o >>= 1) cnt += __shfl_xor_sync(0xffffffffu, cnt, o);
    if (l == 0) sh_w[w] = (float)cnt;
    __syncthreads();
    if (tid == 0) sh_len = (int)(sh_w[0] + sh_w[1] + sh_w[2] + sh_w[3]);
    __syncthreads();
    const int len = sh_len;

    float sc0 = 0.f, sc1 = 0.f, m0 = -FLT_MAX;
    if (tid < len)       { sc0 = g_scores[b * Sc + tid];       m0 = sc0; }
    if (tid + 128 < len) { sc1 = g_scores[b * Sc + tid + 128]; m0 = fmaxf(m0, sc1); }
#pragma unroll
    for (int o = 16; o; o >>= 1) m0 = fmaxf(m0, __shfl_xor_sync(0xffffffffu, m0, o));
    __syncthreads();
    if (l == 0) sh_w[w] = m0;
    __syncthreads();
    const float mx = fmaxf(fmaxf(sh_w[0], sh_w[1]), fmaxf(sh_w[2], sh_w[3]));

    float e0 = (tid < len) ? expf(sc0 - mx) : 0.f;
    float e1 = (tid + 128 < len) ? expf(sc1 - mx) : 0.f;
    float ss = e0 + e1;
#pragma unroll
    for (int o = 16; o; o >>= 1) ss += __shfl_xor_sync(0xffffffffu, ss, o);
    __syncthreads();
    if (l == 0) sh_w[w] = ss;
    __syncthreads();
    const float inv = 1.f / (sh_w[0] + sh_w[1] + sh_w[2] + sh_w[3]);
    sh_attn[tid] = e0 * inv;
    if (tid + 128 < Sc) sh_attn[tid + 128] = e1 * inv;
    __syncthreads();

    // weighted sum, 8 accumulators for MLP
    const float* Xb = X + (size_t)b * Sc * Dc + tid;
    float a0 = 0.f, a1 = 0.f, a2 = 0.f, a3 = 0.f, a4 = 0.f, a5 = 0.f, a6 = 0.f, a7 = 0.f;
    int s = 0;
    for (; s + 8 <= len; s += 8) {
        a0 = fmaf(sh_attn[s + 0], __ldg(&Xb[(s + 0) * Dc]), a0);
        a1 = fmaf(sh_attn[s + 1], __ldg(&Xb[(s + 1) * Dc]), a1);
        a2 = fmaf(sh_attn[s + 2], __ldg(&Xb[(s + 2) * Dc]), a2);
        a3 = fmaf(sh_attn[s + 3], __ldg(&Xb[(s + 3) * Dc]), a3);
        a4 = fmaf(sh_attn[s + 4], __ldg(&Xb[(s + 4) * Dc]), a4);
        a5 = fmaf(sh_attn[s + 5], __ldg(&Xb[(s + 5) * Dc]), a5);
        a6 = fmaf(sh_attn[s + 6], __ldg(&Xb[(s + 6) * Dc]), a6);
        a7 = fmaf(sh_attn[s + 7], __ldg(&Xb[(s + 7) * Dc]), a7);
    }
    for (; s < len; s++) a0 = fmaf(sh_attn[s], __ldg(&Xb[s * Dc]), a0);
    const float ao = ((a0 + a1) + (a2 + a3)) + ((a4 + a5) + (a6 + a7));
    const float lastv = sh_attn[len - 1] * __ldg(&Xb[(len - 1) * Dc]);
    const float outv = ao - lastv;
    sh_outv[tid] = outv;

    const float xi = __ldg(&Xitem[b * Dc + tid]);
    float r0 = lastv * lastv, r1 = outv * outv, r2 = lastv * outv, r3 = ao * xi;
#pragma unroll
    for (int o = 16; o; o >>= 1) {
        r0 += __shfl_xor_sync(0xffffffffu, r0, o);
        r1 += __shfl_xor_sync(0xffffffffu, r1, o);
        r2 += __shfl_xor_sync(0xffffffffu, r2, o);
        r3 += __shfl_xor_sync(0xffffffffu, r3, o);
    }
    if (l == 0) { sh_red[w] = r0; sh_red[4 + w] = r1; sh_red[8 + w] = r2; sh_red[12 + w] = r3; }
    __syncthreads();
    if (tid < 4)
        sh_res[tid] = sh_red[tid * 4] + sh_red[tid * 4 + 1] + sh_red[tid * 4 + 2] + sh_red[tid * 4 + 3];
    __syncthreads();

    const float normOut = sqrtf(fmaxf(sh_res[1], 1e-12f));

    out[b * (Dc + 1) + tid] = ao;
    if (tid == 0) {
        out[b * (Dc + 1) + Dc] = sh_res[3];
        const float cosp = sh_res[2] / (sqrtf(fmaxf(sh_res[0], 1e-12f)) * normOut);
        const float pl = (1.f - cosp) * 0.5f;
        g_posloss[b] = softplus_f(-pl);
    }

    const float o0 = sh_outv[4 * l], o1 = sh_outv[4 * l + 1];
    const float o2 = sh_outv[4 * l + 2], o3 = sh_outv[4 * l + 3];
    const float4* Ob = (const float4*)(origin + (size_t)b * Nc * Dc);
    float nloss = 0.f;
    for (int n = w; n < Nc; n += 4) {
        const float4 og = Ob[n * 32 + l];
        float dot = og.x * o0 + og.y * o1 + og.z * o2 + og.w * o3;
        float nn = og.x * og.x + og.y * og.y + og.z * og.z + og.w * og.w;
#pragma unroll
        for (int o = 16; o; o >>= 1) {
            dot += __shfl_xor_sync(0xffffffffu, dot, o);
            nn  += __shfl_xor_sync(0xffffffffu, nn, o);
        }
        const float cosn = dot / (sqrtf(fmaxf(nn, 1e-12f)) * normOut);
        nloss += softplus_f((1.f - cosn) * 0.5f);
    }
    __syncthreads();
    if (l == 0) sh_w[w] = nloss;
    __syncthreads();
    if (tid == 0) g_negsum[b] = sh_w[0] + sh_w[1] + sh_w[2] + sh_w[3];
}

// ===================== aux write =====================
__global__ void k3_aux(float* __restrict__ out) {
    __shared__ float sw[32];
    const int tid = threadIdx.x;
    float v = g_posloss[tid];
#pragma unroll
    for (int o = 16; o; o >>= 1) v += __shfl_xor_sync(0xffffffffu, v, o);
    if ((tid & 31) == 0) sw[tid >> 5] = v;
    __syncthreads();
    if (tid < 32) {
        float v2 = sw[tid];
#pragma unroll
        for (int o = 16; o; o >>= 1) v2 += __shfl_xor_sync(0xffffffffu, v2, o);
        if (tid == 0) sw[0] = v2;
    }
    __syncthreads();
    out[OUT_CONCAT + tid] = sw[0] + g_negsum[tid];
}

extern "C" void kernel_launch(void* const* d_in, const int* in_sizes, int n_in,
                              void* d_out, int out_size) {
    const float* X      = (const float*)d_in[0];
    const float* pos    = (const float*)d_in[1];
    const float* Xitem  = (const float*)d_in[2];
    const void*  mask   = d_in[3];
    const float* origin = (const float*)d_in[4];
    const float* Wp     = (const float*)d_in[5];
    const float* We     = (const float*)d_in[6];
    const float* z      = (const float*)d_in[7];
    float* out = (float*)d_out;

    cudaFuncSetAttribute(k1_mma, cudaFuncAttributeMaxDynamicSharedMemorySize, SMEM_K1);

    k_detect<<<1, 256>>>((const unsigned int*)mask);
    k0_P<<<Sc, Hc>>>(pos, Wp);
    k1_mma<<<148, 256, SMEM_K1>>>(X, We, z);
    k2_finalize<<<Bc, Dc>>>(X, mask, Xitem, origin, out);
    k3_aux<<<1, Bc>>>(out);
}

// round 5
// speedup vs baseline: 2.8435x; 1.1505x over previous
#include <cuda_runtime.h>
#include <cuda_bf16.h>
#include <float.h>
#include <math.h>
#include <cstdint>

// Problem constants
constexpr int Bc = 1024;
constexpr int Sc = 200;
constexpr int Dc = 128;
constexpr int Hc = 128;
constexpr int Nc = 64;
constexpr int ROWS = Bc * Sc;             // 204800
constexpr int TILES = ROWS / 128;         // 1600
constexpr int OUT_CONCAT = Bc * (Dc + 1); // 132096

// Scratch
__device__ float g_P[Sc * Hc];
__device__ float g_scores[ROWS];
__device__ float g_posloss[Bc];
__device__ float g_negsum[Bc];
__device__ int   g_flags = 0;   // bit0 = bad (uint8), bit1 = f32; reset by k3

__device__ __forceinline__ uint32_t smem_u32(const void* p) {
    uint32_t a;
    asm("{ .reg .u64 t; cvta.to.shared.u64 t, %1; cvt.u32.u64 %0, t; }" : "=r"(a) : "l"(p));
    return a;
}

#define LDMX4(r0, r1, r2, r3, addr) \
    asm volatile("ldmatrix.sync.aligned.m8n8.x4.shared.b16 {%0,%1,%2,%3}, [%4];" \
        : "=r"(r0), "=r"(r1), "=r"(r2), "=r"(r3) : "r"(addr))
#define LDMX2(r0, r1, addr) \
    asm volatile("ldmatrix.sync.aligned.m8n8.x2.shared.b16 {%0,%1}, [%2];" \
        : "=r"(r0), "=r"(r1) : "r"(addr))
#define MMA16816(c, a, b) \
    asm volatile("mma.sync.aligned.m16n8k16.row.col.f32.bf16.bf16.f32 " \
        "{%0,%1,%2,%3},{%4,%5,%6,%7},{%8,%9},{%0,%1,%2,%3};" \
        : "+f"((c)[0]), "+f"((c)[1]), "+f"((c)[2]), "+f"((c)[3]) \
        : "r"((a)[0]), "r"((a)[1]), "r"((a)[2]), "r"((a)[3]), "r"((b)[0]), "r"((b)[1]))

__device__ __forceinline__ uint32_t swz(int row, int chunk) {
    return (uint32_t)(row * 256 + ((chunk ^ (row & 7)) << 4));
}

__device__ __forceinline__ float softplus_f(float x) {
    return fmaxf(x, 0.f) + log1pf(expf(-fabsf(x)));
}
__device__ __forceinline__ float tanh_fast(float x) {
    float t;
    asm("tanh.approx.f32 %0, %1;" : "=f"(t) : "f"(x));
    return t;
}
__device__ __forceinline__ int mask_at(const void* m, int idx, int mode) {
    if (mode == 2) return ((const unsigned char*)m)[idx] != 0;
    if (mode == 1) return ((const float*)m)[idx] != 0.f;
    return ((const int*)m)[idx] != 0;
}

// ===================== P rows + fused mask-dtype detection =====================
// grid = 200 blocks x 128 threads. Block s computes P[s]; threads also scan a
// uint4 slice of the first B*S bytes of the mask for dtype detection.
__global__ void k0_P(const float* __restrict__ pos, const float* __restrict__ Wp,
                     const uint4* __restrict__ mraw) {
    const int s = blockIdx.x, h = threadIdx.x;
    // dtype scan: 204800 B = 12800 uint4; 25600 threads
    const int i = s * 128 + h;
    if (i < (Bc * Sc) / 16) {
        uint4 v = mraw[i];
        int fl = 0;
        uint32_t ws[4] = {v.x, v.y, v.z, v.w};
#pragma unroll
        for (int j = 0; j < 4; j++) {
            if (ws[j] == 0x3F800000u) fl |= 2;
            else if (ws[j] > 1u) fl |= 1;
        }
        if (fl) atomicOr(&g_flags, fl);
    }
    float acc = 0.f;
#pragma unroll 8
    for (int d = 0; d < Dc; d++)
        acc = fmaf(__ldg(&pos[s * Dc + d]), __ldg(&Wp[d * Hc + h]), acc);
    g_P[s * Hc + h] = acc;
}

// ===================== mma.sync score kernel =====================
constexpr int OFF_AHI = 0;
constexpr int OFF_ALO = 32768;
constexpr int OFF_RED = 65536;                  // 128*9*4 = 4608
constexpr int SMEM_K1 = OFF_RED + 128 * 9 * 4;  // 70144

// fast fp32 -> bf16 hi/lo split; hi = top-16-bit truncation
__device__ __forceinline__ void split4(float4 v, uint2& hh, uint2& ll) {
    uint32_t ux = __float_as_uint(v.x), uy = __float_as_uint(v.y);
    uint32_t uz = __float_as_uint(v.z), uw = __float_as_uint(v.w);
    hh.x = __byte_perm(ux, uy, 0x7632);
    hh.y = __byte_perm(uz, uw, 0x7632);
    float lx = v.x - __uint_as_float(ux & 0xFFFF0000u);
    float ly = v.y - __uint_as_float(uy & 0xFFFF0000u);
    float lz = v.z - __uint_as_float(uz & 0xFFFF0000u);
    float lw = v.w - __uint_as_float(uw & 0xFFFF0000u);
    asm("cvt.rn.bf16x2.f32 %0, %1, %2;" : "=r"(ll.x) : "f"(ly), "f"(lx));
    asm("cvt.rn.bf16x2.f32 %0, %1, %2;" : "=r"(ll.y) : "f"(lw), "f"(lz));
}

__global__ void __launch_bounds__(256, 1)
k1_mma(const float* __restrict__ X, const float* __restrict__ We, const float* __restrict__ z) {
    extern __shared__ char smc[];
    const uint32_t smb = smem_u32(smc);
    float* red = (float*)(smc + OFF_RED);
    const int tid = threadIdx.x;
    const int wid = tid >> 5, l = tid & 31;
    const int bn = wid * 16;

    // ---- stage WeT hi/lo, load B fragments ----
    for (int i = tid; i < Dc * Hc; i += 256) {
        int d = i >> 7, h = i & 127;
        float v = We[i];
        __nv_bfloat16 hi = __float2bfloat16(v);
        __nv_bfloat16 lo = __float2bfloat16(v - __bfloat162float(hi));
        uint32_t a = swz(h, d >> 3) + (uint32_t)((d & 7) * 2);
        *(__nv_bfloat16*)(smc + OFF_AHI + a) = hi;
        *(__nv_bfloat16*)(smc + OFF_ALO + a) = lo;
    }
    __syncthreads();

    uint32_t Bh[8][2][2], Bl[8][2][2];
    {
        const int brow = bn + (l & 7);
        const int bc = (l >> 3) & 1;
#pragma unroll
        for (int ks = 0; ks < 8; ks++) {
#pragma unroll
            for (int j = 0; j < 2; j++) {
                uint32_t a = swz(brow + j * 8, 2 * ks + bc);
                LDMX2(Bh[ks][j][0], Bh[ks][j][1], smb + OFF_AHI + a);
                LDMX2(Bl[ks][j][0], Bl[ks][j][1], smb + OFF_ALO + a);
            }
        }
    }
    const int c0 = bn + (l & 3) * 2;
    const float zv0 = __ldg(&z[c0]),     zv1 = __ldg(&z[c0 + 1]);
    const float zv2 = __ldg(&z[c0 + 8]), zv3 = __ldg(&z[c0 + 9]);
    __syncthreads();

    const int arow_off = (l & 7) + ((l >> 3) & 1) * 8;
    const int achk_off = (l >> 4) & 1;

    const int GD = gridDim.x;
    int t = blockIdx.x;
    float4 pf[16];
    if (t < TILES) {
        const float4* Xg = (const float4*)(X + (size_t)t * (128 * 128));
#pragma unroll
        for (int jj = 0; jj < 16; jj++) pf[jj] = Xg[tid + jj * 256];
    }

    for (; t < TILES; t += GD) {
        // ---- convert + store prefetched tile ----
#pragma unroll
        for (int jj = 0; jj < 16; jj++) {
            int i4 = tid + jj * 256;
            int elem = i4 * 4;
            int row = elem >> 7, col = elem & 127;
            uint32_t a = swz(row, col >> 3) + (uint32_t)((col & 7) * 2);
            uint2 hh, ll;
            split4(pf[jj], hh, ll);
            *(uint2*)(smc + OFF_AHI + a) = hh;
            *(uint2*)(smc + OFF_ALO + a) = ll;
        }
        __syncthreads();

        // ---- prefetch next tile NOW: latency hides behind the whole GEMM ----
        const int tn = t + GD;
        if (tn < TILES) {
            const float4* Xg = (const float4*)(X + (size_t)tn * (128 * 128));
#pragma unroll
            for (int jj = 0; jj < 16; jj++) pf[jj] = Xg[tid + jj * 256];
        }

        // ---- GEMM: C = Xhi*Whi + Xhi*Wlo + Xlo*Whi ----
        float C[8][2][4];
#pragma unroll
        for (int f = 0; f < 8; f++)
#pragma unroll
            for (int j = 0; j < 2; j++)
#pragma unroll
                for (int q = 0; q < 4; q++) C[f][j][q] = 0.f;

#pragma unroll
        for (int ks = 0; ks < 8; ks++) {
            uint32_t A[8][4];
#pragma unroll
            for (int f = 0; f < 8; f++) {
                uint32_t a = swz(f * 16 + arow_off, 2 * ks + achk_off);
                LDMX4(A[f][0], A[f][1], A[f][2], A[f][3], smb + OFF_AHI + a);
            }
#pragma unroll
            for (int f = 0; f < 8; f++) {
                MMA16816(C[f][0], A[f], Bh[ks][0]);
                MMA16816(C[f][1], A[f], Bh[ks][1]);
                MMA16816(C[f][0], A[f], Bl[ks][0]);
                MMA16816(C[f][1], A[f], Bl[ks][1]);
            }
#pragma unroll
            for (int f = 0; f < 8; f++) {
                uint32_t a = swz(f * 16 + arow_off, 2 * ks + achk_off);
                LDMX4(A[f][0], A[f][1], A[f][2], A[f][3], smb + OFF_ALO + a);
            }
#pragma unroll
            for (int f = 0; f < 8; f++) {
                MMA16816(C[f][0], A[f], Bh[ks][0]);
                MMA16816(C[f][1], A[f], Bh[ks][1]);
            }
        }

        // ---- epilogue: partial z . tanh(C + P) per warp slice ----
        const int mb = t * 128;
#pragma unroll
        for (int f = 0; f < 8; f++) {
            const int r0 = f * 16 + (l >> 2), r1 = r0 + 8;
            const int s0 = (mb + r0) % Sc, s1 = (mb + r1) % Sc;
            float2 p00 = __ldg((const float2*)&g_P[s0 * Hc + c0]);
            float2 p01 = __ldg((const float2*)&g_P[s0 * Hc + c0 + 8]);
            float2 p10 = __ldg((const float2*)&g_P[s1 * Hc + c0]);
            float2 p11 = __ldg((const float2*)&g_P[s1 * Hc + c0 + 8]);
            float p0 = zv0 * tanh_fast(C[f][0][0] + p00.x) + zv1 * tanh_fast(C[f][0][1] + p00.y)
                     + zv2 * tanh_fast(C[f][1][0] + p01.x) + zv3 * tanh_fast(C[f][1][1] + p01.y);
            float p1 = zv0 * tanh_fast(C[f][0][2] + p10.x) + zv1 * tanh_fast(C[f][0][3] + p10.y)
                     + zv2 * tanh_fast(C[f][1][2] + p11.x) + zv3 * tanh_fast(C[f][1][3] + p11.y);
            p0 += __shfl_xor_sync(0xffffffffu, p0, 1);
            p0 += __shfl_xor_sync(0xffffffffu, p0, 2);
            p1 += __shfl_xor_sync(0xffffffffu, p1, 1);
            p1 += __shfl_xor_sync(0xffffffffu, p1, 2);
            if ((l & 3) == 0) { red[r0 * 9 + wid] = p0; red[r1 * 9 + wid] = p1; }
        }
        __syncthreads();
        if (tid < 128) {
            float s = 0.f;
#pragma unroll
            for (int w = 0; w < 8; w++) s += red[tid * 9 + w];
            g_scores[mb + tid] = s;
        }
        __syncthreads();
    }
}

// ===================== per-batch finalize =====================
__global__ void k2_finalize(const float* __restrict__ X,
                            const void* __restrict__ mask,
                            const float* __restrict__ Xitem,
                            const float* __restrict__ origin,
                            float* __restrict__ out) {
    __shared__ float sh_attn[Sc];
    __shared__ __align__(16) float sh_outv[Dc];
    __shared__ __align__(16) float sh_ws[4 * Dc];
    __shared__ float sh_w[4];
    __shared__ float sh_red[16];
    __shared__ float sh_res[4];
    __shared__ int   sh_len;

    const int b = blockIdx.x, tid = threadIdx.x;
    const int w = tid >> 5, l = tid & 31;
    const int fl = g_flags;
    const int mode = (fl & 1) ? 2 : ((fl & 2) ? 1 : 0);

    int cnt = mask_at(mask, b * Sc + tid, mode);
    if (tid + 128 < Sc) cnt += mask_at(mask, b * Sc + tid + 128, mode);
#pragma unroll
    for (int o = 16; o; o >>= 1) cnt += __shfl_xor_sync(0xffffffffu, cnt, o);
    if (l == 0) sh_w[w] = (float)cnt;
    __syncthreads();
    if (tid == 0) sh_len = (int)(sh_w[0] + sh_w[1] + sh_w[2] + sh_w[3]);
    __syncthreads();
    const int len = sh_len;

    float sc0 = 0.f, sc1 = 0.f, m0 = -FLT_MAX;
    if (tid < len)       { sc0 = g_scores[b * Sc + tid];       m0 = sc0; }
    if (tid + 128 < len) { sc1 = g_scores[b * Sc + tid + 128]; m0 = fmaxf(m0, sc1); }
#pragma unroll
    for (int o = 16; o; o >>= 1) m0 = fmaxf(m0, __shfl_xor_sync(0xffffffffu, m0, o));
    __syncthreads();
    if (l == 0) sh_w[w] = m0;
    __syncthreads();
    const float mx = fmaxf(fmaxf(sh_w[0], sh_w[1]), fmaxf(sh_w[2], sh_w[3]));

    float e0 = (tid < len) ? expf(sc0 - mx) : 0.f;
    float e1 = (tid + 128 < len) ? expf(sc1 - mx) : 0.f;
    float ss = e0 + e1;
#pragma unroll
    for (int o = 16; o; o >>= 1) ss += __shfl_xor_sync(0xffffffffu, ss, o);
    __syncthreads();
    if (l == 0) sh_w[w] = ss;
    __syncthreads();
    const float inv = 1.f / (sh_w[0] + sh_w[1] + sh_w[2] + sh_w[3]);
    sh_attn[tid] = e0 * inv;
    if (tid + 128 < Sc) sh_attn[tid + 128] = e1 * inv;
    __syncthreads();

    // ---- weighted sum: warp w -> rows = w (mod 4), lane l -> d = 4l..4l+3 ----
    const float4* Xb4 = (const float4*)(X + (size_t)b * Sc * Dc) + l;
    float4 acc0 = make_float4(0.f, 0.f, 0.f, 0.f);
    float4 acc1 = make_float4(0.f, 0.f, 0.f, 0.f);
    int r = w;
    for (; r + 4 < len; r += 8) {
        const float aw0 = sh_attn[r], aw1 = sh_attn[r + 4];
        const float4 x0 = __ldg(&Xb4[(size_t)r * 32]);
        const float4 x1 = __ldg(&Xb4[(size_t)(r + 4) * 32]);
        acc0.x = fmaf(aw0, x0.x, acc0.x); acc0.y = fmaf(aw0, x0.y, acc0.y);
        acc0.z = fmaf(aw0, x0.z, acc0.z); acc0.w = fmaf(aw0, x0.w, acc0.w);
        acc1.x = fmaf(aw1, x1.x, acc1.x); acc1.y = fmaf(aw1, x1.y, acc1.y);
        acc1.z = fmaf(aw1, x1.z, acc1.z); acc1.w = fmaf(aw1, x1.w, acc1.w);
    }
    if (r < len) {
        const float aw = sh_attn[r];
        const float4 x0 = __ldg(&Xb4[(size_t)r * 32]);
        acc0.x = fmaf(aw, x0.x, acc0.x); acc0.y = fmaf(aw, x0.y, acc0.y);
        acc0.z = fmaf(aw, x0.z, acc0.z); acc0.w = fmaf(aw, x0.w, acc0.w);
    }
    acc0.x += acc1.x; acc0.y += acc1.y; acc0.z += acc1.z; acc0.w += acc1.w;
    *(float4*)&sh_ws[w * Dc + 4 * l] = acc0;
    __syncthreads();
    const float ao = sh_ws[tid] + sh_ws[Dc + tid] + sh_ws[2 * Dc + tid] + sh_ws[3 * Dc + tid];

    const float lastv = sh_attn[len - 1] * __ldg(&X[(size_t)b * Sc * Dc + (size_t)(len - 1) * Dc + tid]);
    const float outv = ao - lastv;
    sh_outv[tid] = outv;

    const float xi = __ldg(&Xitem[b * Dc + tid]);
    float r0 = lastv * lastv, r1 = outv * outv, r2 = lastv * outv, r3 = ao * xi;
#pragma unroll
    for (int o = 16; o; o >>= 1) {
        r0 += __shfl_xor_sync(0xffffffffu, r0, o);
        r1 += __shfl_xor_sync(0xffffffffu, r1, o);
        r2 += __shfl_xor_sync(0xffffffffu, r2, o);
        r3 += __shfl_xor_sync(0xffffffffu, r3, o);
    }
    if (l == 0) { sh_red[w] = r0; sh_red[4 + w] = r1; sh_red[8 + w] = r2; sh_red[12 + w] = r3; }
    __syncthreads();
    if (tid < 4)
        sh_res[tid] = sh_red[tid * 4] + sh_red[tid * 4 + 1] + sh_red[tid * 4 + 2] + sh_red[tid * 4 + 3];
    __syncthreads();

    const float normOut = sqrtf(fmaxf(sh_res[1], 1e-12f));

    out[b * (Dc + 1) + tid] = ao;
    if (tid == 0) {
        out[b * (Dc + 1) + Dc] = sh_res[3];
        const float cosp = sh_res[2] / (sqrtf(fmaxf(sh_res[0], 1e-12f)) * normOut);
        const float pl = (1.f - cosp) * 0.5f;
        g_posloss[b] = softplus_f(-pl);
    }

    const float o0 = sh_outv[4 * l], o1 = sh_outv[4 * l + 1];
    const float o2 = sh_outv[4 * l + 2], o3 = sh_outv[4 * l + 3];
    const float4* Ob = (const float4*)(origin + (size_t)b * Nc * Dc);
    float nloss = 0.f;
    for (int n = w; n < Nc; n += 4) {
        const float4 og = Ob[n * 32 + l];
        float dot = og.x * o0 + og.y * o1 + og.z * o2 + og.w * o3;
        float nn = og.x * og.x + og.y * og.y + og.z * og.z + og.w * og.w;
#pragma unroll
        for (int o = 16; o; o >>= 1) {
            dot += __shfl_xor_sync(0xffffffffu, dot, o);
            nn  += __shfl_xor_sync(0xffffffffu, nn, o);
        }
        const float cosn = dot / (sqrtf(fmaxf(nn, 1e-12f)) * normOut);
        nloss += softplus_f((1.f - cosn) * 0.5f);
    }
    __syncthreads();
    if (l == 0) sh_w[w] = nloss;
    __syncthreads();
    if (tid == 0) g_negsum[b] = sh_w[0] + sh_w[1] + sh_w[2] + sh_w[3];
}

// ===================== aux write (+ flag reset for next replay) =====================
__global__ void k3_aux(float* __restrict__ out) {
    __shared__ float sw[32];
    const int tid = threadIdx.x;
    float v = g_posloss[tid];
#pragma unroll
    for (int o = 16; o; o >>= 1) v += __shfl_xor_sync(0xffffffffu, v, o);
    if ((tid & 31) == 0) sw[tid >> 5] = v;
    __syncthreads();
    if (tid < 32) {
        float v2 = sw[tid];
#pragma unroll
        for (int o = 16; o; o >>= 1) v2 += __shfl_xor_sync(0xffffffffu, v2, o);
        if (tid == 0) sw[0] = v2;
    }
    __syncthreads();
    out[OUT_CONCAT + tid] = sw[0] + g_negsum[tid];
    if (tid == 0) g_flags = 0;   // reset for next graph replay
}

extern "C" void kernel_launch(void* const* d_in, const int* in_sizes, int n_in,
                              void* d_out, int out_size) {
    const float* X      = (const float*)d_in[0];
    const float* pos    = (const float*)d_in[1];
    const float* Xitem  = (const float*)d_in[2];
    const void*  mask   = d_in[3];
    const float* origin = (const float*)d_in[4];
    const float* Wp     = (const float*)d_in[5];
    const float* We     = (const float*)d_in[6];
    const float* z      = (const float*)d_in[7];
    float* out = (float*)d_out;

    cudaFuncSetAttribute(k1_mma, cudaFuncAttributeMaxDynamicSharedMemorySize, SMEM_K1);

    k0_P<<<Sc, Hc>>>(pos, Wp, (const uint4*)mask);
    k1_mma<<<148, 256, SMEM_K1>>>(X, We, z);
    k2_finalize<<<Bc, Dc>>>(X, mask, Xitem, origin, out);
    k3_aux<<<1, Bc>>>(out);
}